// round 13
// baseline (speedup 1.0000x reference)
#include <cuda_runtime.h>
#include <cstdint>

// ============================================================================
// PuzzleSim: out[p] = max over (n,q) of <img_n[:,p], refs_n[n,:,q]>
// R11 = R10 with the GEMM restructured for boundary-bubble removal:
//  - 288 persistent CTAs (18 bm x 16 groups x 2 bn each): single wave, A
//    loaded once per CTA, 36 B-tiles streamed continuously.
//  - CP_WAIT+__syncthreads moved between np3's mmas and np3's fold, followed
//    by a preload of the NEXT tile's np0 B-fragments (stage t+1 is visible
//    there), so no iteration starts with an exposed LDS->mma chain.
// int8 IMMA 3-pass: S = 128*Sum(hi*hi) + Sum(hi*lo + lo*hi); sim ~ S/2^21.
// ============================================================================

#define NREF    32
#define CCH     128
#define HW      2304            // 48*48
#define MT      128
#define NT      128
#define NTILES  (HW / NT)       // 18
#define MTILES  (HW / MT)       // 18
#define BN_PER_CTA 2
#define STREAM_T (NTILES * BN_PER_CTA)          // 36 tiles per CTA
#define NBLK_G  (MTILES * (NREF / BN_PER_CTA))  // 288 CTAs, single wave
#define TILE_U32 8192           // one (hi+lo) frag-linear tile = 32KB
#define BSTAGE_BYTES 32768
#define DSMEM_GEMM (3 * BSTAGE_BYTES)   // 96KB -> 2 CTAs/SM
#define PREP_SMEM  (2 * 128 * 132)      // 33792B

// ---- device scratch ----
// per-tile layout (u32): [pass(2)][blk(8)][ks(4)][lane(32)][reg(4)]
//   A: blk = m16 index (8 x 16 rows);  B: blk = nf-pair (8 x 16 cols)
__device__ uint32_t g_imgA[(size_t)MTILES * TILE_U32];
__device__ uint32_t g_refsQ[(size_t)(NREF * NTILES) * TILE_U32];
__device__ int g_pmax[HW];
__device__ int g_done;

// ============================================================================
// helpers
// ============================================================================
__device__ __forceinline__ uint32_t smem_u32(const void* p) {
    uint32_t a;
    asm("{ .reg .u64 t; cvta.to.shared.u64 t, %1; cvt.u32.u64 %0, t; }"
        : "=r"(a) : "l"(p));
    return a;
}
// accumulate: D = A*B + D
__device__ __forceinline__ void mma_s8(int* c, const uint32_t* a,
                                       const uint32_t* b) {
    asm volatile(
        "mma.sync.aligned.m16n8k32.row.col.s32.s8.s8.s32 "
        "{%0,%1,%2,%3}, {%4,%5,%6,%7}, {%8,%9}, {%0,%1,%2,%3};"
        : "+r"(c[0]), "+r"(c[1]), "+r"(c[2]), "+r"(c[3])
        : "r"(a[0]), "r"(a[1]), "r"(a[2]), "r"(a[3]), "r"(b[0]), "r"(b[1]));
}
// initialize: D = A*B + 0
__device__ __forceinline__ void mma_s8_zc(int* d, const uint32_t* a,
                                          const uint32_t* b) {
    asm volatile(
        "mma.sync.aligned.m16n8k32.row.col.s32.s8.s8.s32 "
        "{%0,%1,%2,%3}, {%4,%5,%6,%7}, {%8,%9}, {%10,%10,%10,%10};"
        : "=r"(d[0]), "=r"(d[1]), "=r"(d[2]), "=r"(d[3])
        : "r"(a[0]), "r"(a[1]), "r"(a[2]), "r"(a[3]), "r"(b[0]), "r"(b[1]),
          "r"(0));
}
#define CP_ASYNC16(dst, src) \
    asm volatile("cp.async.cg.shared.global [%0], [%1], 16;" \
                 :: "r"(dst), "l"(src) : "memory")
#define CP_COMMIT()  asm volatile("cp.async.commit_group;" ::: "memory")
#define CP_WAIT(n)   asm volatile("cp.async.wait_group %0;" :: "n"(n) : "memory")
#define LDS128(r0, r1, r2, r3, addr) \
    asm volatile("ld.shared.v4.b32 {%0,%1,%2,%3}, [%4];" \
                 : "=r"(r0), "=r"(r1), "=r"(r2), "=r"(r3) : "r"(addr))

// quantize a normalized value: q = round(v*2^14), hi=(q+64)>>7, lo=q-128*hi
__device__ __forceinline__ void quant14(float v, char& hi, char& lo) {
    int q = __float2int_rn(v * 16384.f);
    q = max(min(q, 16319), -16319);
    int h = (q + 64) >> 7;
    hi = (char)h;
    lo = (char)(q - (h << 7));
}

// ============================================================================
// K1: fused prep (unchanged from R10). 594 blocks x 512 thr; 4 threads per
// position, shfl-reduce norm.
// ============================================================================
__global__ __launch_bounds__(512) void k_prep(const float* __restrict__ refs,
                                              const float* __restrict__ img) {
    extern __shared__ char sc[];
    char* sh = sc;
    char* sl = sc + 128 * 132;
    const int tid = threadIdx.x;
    const int bid = blockIdx.x;
    const int pos = tid >> 2;
    const int quarter = tid & 3;
    const bool is_img = bid < MTILES;

    const float* base;
    if (is_img) {
        const int p = bid * 128 + pos;
        if (quarter == 0) {
            g_pmax[p] = (int)0x80000000;
            if (p == 0) g_done = 0;
        }
        base = img + p;
    } else {
        const int rb = bid - MTILES;
        const int bn = rb / NTILES;
        const int q = (rb % NTILES) * 128 + pos;
        base = refs + (size_t)bn * CCH * HW + q;
    }
    const float* cb = base + (size_t)(quarter * 32) * HW;

    float v[32];
    float ss = 0.f;
    #pragma unroll 8
    for (int c = 0; c < 32; c++) {
        v[c] = cb[(size_t)c * HW];
        ss += v[c] * v[c];
    }
    ss += __shfl_xor_sync(0xffffffffu, ss, 1);
    ss += __shfl_xor_sync(0xffffffffu, ss, 2);
    float scale = 1.0f / fmaxf(sqrtf(ss), 1e-12f);

    #pragma unroll 8
    for (int c = 0; c < 32; c++) {
        char h, l;
        quant14(v[c] * scale, h, l);
        sh[pos * 132 + quarter * 32 + c] = h;
        sl[pos * 132 + quarter * 32 + c] = l;
    }
    __syncthreads();

    if (is_img) {
        uint32_t* dst = g_imgA + (size_t)bid * TILE_U32;
        #pragma unroll 4
        for (int w = 0; w < 16; w++) {
            int idx = w * 512 + tid;
            int reg = idx & 3, lane = (idx >> 2) & 31, ks = (idx >> 7) & 3;
            int m16 = (idx >> 9) & 7, pass = idx >> 12;
            int row = 16 * m16 + (lane >> 2) + 8 * (reg & 1);
            int k = 32 * ks + 4 * (lane & 3) + 16 * (reg >> 1);
            const char* s = pass ? sl : sh;
            dst[idx] = *(const uint32_t*)(s + row * 132 + k);
        }
    } else {
        uint32_t* dst = g_refsQ + (size_t)(bid - MTILES) * TILE_U32;
        #pragma unroll 4
        for (int w = 0; w < 16; w++) {
            int idx = w * 512 + tid;
            int reg = idx & 3, lane = (idx >> 2) & 31, ks = (idx >> 7) & 3;
            int nfp = (idx >> 9) & 7, pass = idx >> 12;
            int col = 16 * nfp + (lane >> 2) + 8 * (reg >> 1);
            int k = 32 * ks + 4 * (lane & 3) + 16 * (reg & 1);
            const char* s = pass ? sl : sh;
            dst[idx] = *(const uint32_t*)(s + col * 132 + k);
        }
    }
}

// ============================================================================
// K2: persistent GEMM+max. 288 CTAs, 2/SM, single wave.
// CTA: bm = bid%18, bn0 = (bid/18)*2; streams 36 consecutive B-tiles.
// ============================================================================
__device__ __forceinline__ void fill_b_async(uint32_t dst,
                                             const uint32_t* __restrict__ src,
                                             int tid) {
    const char* s = (const char*)src;
    #pragma unroll
    for (int i = 0; i < 8; i++)
        CP_ASYNC16(dst + i * 4096 + tid * 16, s + i * 4096 + tid * 16);
}

__global__ __launch_bounds__(256, 2) void k_gemm_max(float* __restrict__ out) {
    extern __shared__ char sm[];
    __shared__ int s_last;
    const int tid = threadIdx.x, wid = tid >> 5, lane = tid & 31;
    const int wm = wid >> 1, wn = wid & 1;
    const uint32_t Bring = smem_u32(sm);         // 3 x 32KB

    const int bm = blockIdx.x % MTILES;
    const int bn0 = (blockIdx.x / MTILES) * BN_PER_CTA;
    const int p0 = bm * MT;
    const uint32_t* imgT = g_imgA + (size_t)bm * TILE_U32;
    const uint32_t* refT = g_refsQ + (size_t)(bn0 * NTILES) * TILE_U32;

    // prologue: fill tiles 0 and 1 as two commit groups
    fill_b_async(Bring, refT, tid);
    CP_COMMIT();
    fill_b_async(Bring + BSTAGE_BYTES, refT + TILE_U32, tid);
    CP_COMMIT();

    // A hi+lo fragments -> registers (live whole kernel)
    uint32_t ahi[2][4][4], alo[2][4][4];
    #pragma unroll
    for (int mf = 0; mf < 2; mf++)
        #pragma unroll
        for (int ks = 0; ks < 4; ks++) {
            const size_t fi = (size_t)(((wm * 2 + mf) * 4 + ks) * 32 + lane) * 4;
            const uint4 wh = *(const uint4*)(imgT + fi);
            const uint4 wl = *(const uint4*)(imgT + 4096 + fi);
            ahi[mf][ks][0] = wh.x; ahi[mf][ks][1] = wh.y;
            ahi[mf][ks][2] = wh.z; ahi[mf][ks][3] = wh.w;
            alo[mf][ks][0] = wl.x; alo[mf][ks][1] = wl.y;
            alo[mf][ks][2] = wl.z; alo[mf][ks][3] = wl.w;
        }

    const uint32_t bOffW = (uint32_t)((wn * 4) * 4 * 32 + lane) * 16;

    int rmax0[2], rmax1[2];
    #pragma unroll
    for (int mf = 0; mf < 2; mf++) { rmax0[mf] = (int)0x80000000; rmax1[mf] = (int)0x80000000; }

    // prologue sync: tile 0 visible, then preload its np0 fragments
    CP_WAIT(1);
    __syncthreads();
    uint32_t pbh[4], pbl[4];
    {
        const uint32_t Bh = Bring + bOffW;
        LDS128(pbh[0], pbh[1], pbh[2], pbh[3], Bh);
        LDS128(pbl[0], pbl[1], pbl[2], pbl[3], Bh + 16384);
    }

    #pragma unroll 1
    for (int s = 0; s < STREAM_T; s++) {
        // fill stage (s+2)%3; its old readers (tile s-1) passed the mid-iter
        // barrier of s-1. One commit group per iteration (empty at tail ok).
        if (s + 2 < STREAM_T)
            fill_b_async(Bring + (uint32_t)((s + 2) % 3) * BSTAGE_BYTES,
                         refT + (size_t)(s + 2) * TILE_U32, tid);
        CP_COMMIT();

        const uint32_t Bhi = Bring + (uint32_t)(s % 3) * BSTAGE_BYTES + bOffW;
        const uint32_t Blo = Bhi + 16384;

        #pragma unroll
        for (int np = 0; np < 4; np++) {
            int hh[2][2][4], xx[2][2][4];
            #pragma unroll
            for (int ks = 0; ks < 4; ks++) {
                uint32_t bh[4], bl[4];
                if (np == 0 && ks == 0) {
                    bh[0] = pbh[0]; bh[1] = pbh[1]; bh[2] = pbh[2]; bh[3] = pbh[3];
                    bl[0] = pbl[0]; bl[1] = pbl[1]; bl[2] = pbl[2]; bl[3] = pbl[3];
                } else {
                    const uint32_t fo = (uint32_t)((np * 4 + ks) * 32) * 16;
                    LDS128(bh[0], bh[1], bh[2], bh[3], Bhi + fo);
                    LDS128(bl[0], bl[1], bl[2], bl[3], Blo + fo);
                }
                #pragma unroll
                for (int half = 0; half < 2; half++) {
                    const uint32_t* bhp = bh + 2 * half;
                    const uint32_t* blp = bl + 2 * half;
                    #pragma unroll
                    for (int mf = 0; mf < 2; mf++) {
                        if (ks == 0) {
                            mma_s8_zc(hh[mf][half], ahi[mf][0], bhp);
                            mma_s8_zc(xx[mf][half], ahi[mf][0], blp);
                            mma_s8(xx[mf][half], alo[mf][0], bhp);
                        } else {
                            mma_s8(hh[mf][half], ahi[mf][ks], bhp);
                            mma_s8(xx[mf][half], ahi[mf][ks], blp);
                            mma_s8(xx[mf][half], alo[mf][ks], bhp);
                        }
                    }
                }
            }

            if (np == 3) {
                // mid-iter sync: tile s+1's fill group completed under WAIT(1);
                // barrier publishes it and retires all reads of tile s.
                CP_WAIT(1);
                __syncthreads();
                if (s + 1 < STREAM_T) {
                    const uint32_t Bn = Bring +
                        (uint32_t)((s + 1) % 3) * BSTAGE_BYTES + bOffW;
                    LDS128(pbh[0], pbh[1], pbh[2], pbh[3], Bn);
                    LDS128(pbl[0], pbl[1], pbl[2], pbl[3], Bn + 16384);
                }
            }

            // fold this np-group (overlaps preload LDS latency at np3)
            #pragma unroll
            for (int mf = 0; mf < 2; mf++)
                #pragma unroll
                for (int h = 0; h < 2; h++) {
                    int s0 = hh[mf][h][0] * 128 + xx[mf][h][0];
                    int s1 = hh[mf][h][1] * 128 + xx[mf][h][1];
                    int s2 = hh[mf][h][2] * 128 + xx[mf][h][2];
                    int s3 = hh[mf][h][3] * 128 + xx[mf][h][3];
                    rmax0[mf] = max(rmax0[mf], max(s0, s1));
                    rmax1[mf] = max(rmax1[mf], max(s2, s3));
                }
        }
    }

    // per-CTA epilogue: reduce 4 lanes sharing a row, one atomic per row
    #pragma unroll
    for (int mf = 0; mf < 2; mf++) {
        int m0 = rmax0[mf], m1 = rmax1[mf];
        m0 = max(m0, __shfl_xor_sync(0xffffffffu, m0, 1));
        m0 = max(m0, __shfl_xor_sync(0xffffffffu, m0, 2));
        m1 = max(m1, __shfl_xor_sync(0xffffffffu, m1, 1));
        m1 = max(m1, __shfl_xor_sync(0xffffffffu, m1, 2));
        if ((lane & 3) == 0) {
            int row = p0 + wm * 32 + mf * 16 + (lane >> 2);
            atomicMax(&g_pmax[row], m0);
            atomicMax(&g_pmax[row + 8], m1);
        }
    }

    // last-block final decode
    __threadfence();
    if (tid == 0) s_last = (atomicAdd(&g_done, 1) == NBLK_G - 1);
    __syncthreads();
    if (s_last) {
        #pragma unroll
        for (int i = 0; i < HW / 256; i++) {
            int p = i * 256 + tid;
            int s = atomicMax(&g_pmax[p], (int)0x80000000);
            out[p] = (float)s * (1.0f / 2097152.0f);
        }
    }
}

// ============================================================================
extern "C" void kernel_launch(void* const* d_in, const int* in_sizes, int n_in,
                              void* d_out, int out_size) {
    const float* refs = (const float*)d_in[0];
    const float* img  = (const float*)d_in[1];
    float* out = (float*)d_out;

    cudaFuncSetAttribute(k_gemm_max, cudaFuncAttributeMaxDynamicSharedMemorySize,
                         DSMEM_GEMM);

    k_prep<<<MTILES + NREF * NTILES, 512, PREP_SMEM>>>(refs, img);
    k_gemm_max<<<NBLK_G, 256, DSMEM_GEMM>>>(out);
}

// round 14
// speedup vs baseline: 1.0191x; 1.0191x over previous
#include <cuda_runtime.h>
#include <cstdint>

// ============================================================================
// PuzzleSim: out[p] = max over (n,q) of <img_n[:,p], refs_n[n,:,q]>
// R14 = R10 macro-structure (576 CTAs, 18-tile stream, work-stealing balance)
// + the mid-iteration barrier/preload from R13 (the part that helped):
// CP_WAIT+__syncthreads sits between np3's mmas and np3's fold, followed by a
// register preload of the NEXT tile's np0 B-fragments, so no iteration starts
// with an exposed LDS->mma chain and the barrier is off the critical path.
// int8 IMMA 3-pass: S = 128*Sum(hi*hi) + Sum(hi*lo + lo*hi); sim ~ S/2^21.
// ============================================================================

#define NREF    32
#define CCH     128
#define HW      2304            // 48*48
#define MT      128
#define NT      128
#define NTILES  (HW / NT)       // 18
#define MTILES  (HW / MT)       // 18
#define NBLK    (MTILES * NREF) // 576
#define TILE_U32 8192           // one (hi+lo) frag-linear tile = 32KB
#define BSTAGE_BYTES 32768
#define DSMEM_GEMM (3 * BSTAGE_BYTES)   // 96KB -> 2 CTAs/SM
#define PREP_SMEM  (2 * 128 * 132)      // 33792B

// ---- device scratch ----
// per-tile layout (u32): [pass(2)][blk(8)][ks(4)][lane(32)][reg(4)]
//   A: blk = m16 index (8 x 16 rows);  B: blk = nf-pair (8 x 16 cols)
__device__ uint32_t g_imgA[(size_t)MTILES * TILE_U32];
__device__ uint32_t g_refsQ[(size_t)(NREF * NTILES) * TILE_U32];
__device__ int g_pmax[HW];
__device__ int g_done;

// ============================================================================
// helpers
// ============================================================================
__device__ __forceinline__ uint32_t smem_u32(const void* p) {
    uint32_t a;
    asm("{ .reg .u64 t; cvta.to.shared.u64 t, %1; cvt.u32.u64 %0, t; }"
        : "=r"(a) : "l"(p));
    return a;
}
// accumulate: D = A*B + D
__device__ __forceinline__ void mma_s8(int* c, const uint32_t* a,
                                       const uint32_t* b) {
    asm volatile(
        "mma.sync.aligned.m16n8k32.row.col.s32.s8.s8.s32 "
        "{%0,%1,%2,%3}, {%4,%5,%6,%7}, {%8,%9}, {%0,%1,%2,%3};"
        : "+r"(c[0]), "+r"(c[1]), "+r"(c[2]), "+r"(c[3])
        : "r"(a[0]), "r"(a[1]), "r"(a[2]), "r"(a[3]), "r"(b[0]), "r"(b[1]));
}
// initialize: D = A*B + 0
__device__ __forceinline__ void mma_s8_zc(int* d, const uint32_t* a,
                                          const uint32_t* b) {
    asm volatile(
        "mma.sync.aligned.m16n8k32.row.col.s32.s8.s8.s32 "
        "{%0,%1,%2,%3}, {%4,%5,%6,%7}, {%8,%9}, {%10,%10,%10,%10};"
        : "=r"(d[0]), "=r"(d[1]), "=r"(d[2]), "=r"(d[3])
        : "r"(a[0]), "r"(a[1]), "r"(a[2]), "r"(a[3]), "r"(b[0]), "r"(b[1]),
          "r"(0));
}
#define CP_ASYNC16(dst, src) \
    asm volatile("cp.async.cg.shared.global [%0], [%1], 16;" \
                 :: "r"(dst), "l"(src) : "memory")
#define CP_COMMIT()  asm volatile("cp.async.commit_group;" ::: "memory")
#define CP_WAIT(n)   asm volatile("cp.async.wait_group %0;" :: "n"(n) : "memory")
#define LDS128(r0, r1, r2, r3, addr) \
    asm volatile("ld.shared.v4.b32 {%0,%1,%2,%3}, [%4];" \
                 : "=r"(r0), "=r"(r1), "=r"(r2), "=r"(r3) : "r"(addr))

// quantize a normalized value: q = round(v*2^14), hi=(q+64)>>7, lo=q-128*hi
__device__ __forceinline__ void quant14(float v, char& hi, char& lo) {
    int q = __float2int_rn(v * 16384.f);
    q = max(min(q, 16319), -16319);
    int h = (q + 64) >> 7;
    hi = (char)h;
    lo = (char)(q - (h << 7));
}

// ============================================================================
// K1: fused prep (unchanged from R10). 594 blocks x 512 thr; 4 threads per
// position, shfl-reduce norm.
// ============================================================================
__global__ __launch_bounds__(512) void k_prep(const float* __restrict__ refs,
                                              const float* __restrict__ img) {
    extern __shared__ char sc[];
    char* sh = sc;
    char* sl = sc + 128 * 132;
    const int tid = threadIdx.x;
    const int bid = blockIdx.x;
    const int pos = tid >> 2;
    const int quarter = tid & 3;
    const bool is_img = bid < MTILES;

    const float* base;
    if (is_img) {
        const int p = bid * 128 + pos;
        if (quarter == 0) {
            g_pmax[p] = (int)0x80000000;
            if (p == 0) g_done = 0;
        }
        base = img + p;
    } else {
        const int rb = bid - MTILES;
        const int bn = rb / NTILES;
        const int q = (rb % NTILES) * 128 + pos;
        base = refs + (size_t)bn * CCH * HW + q;
    }
    const float* cb = base + (size_t)(quarter * 32) * HW;

    float v[32];
    float ss = 0.f;
    #pragma unroll 8
    for (int c = 0; c < 32; c++) {
        v[c] = cb[(size_t)c * HW];
        ss += v[c] * v[c];
    }
    ss += __shfl_xor_sync(0xffffffffu, ss, 1);
    ss += __shfl_xor_sync(0xffffffffu, ss, 2);
    float scale = 1.0f / fmaxf(sqrtf(ss), 1e-12f);

    #pragma unroll 8
    for (int c = 0; c < 32; c++) {
        char h, l;
        quant14(v[c] * scale, h, l);
        sh[pos * 132 + quarter * 32 + c] = h;
        sl[pos * 132 + quarter * 32 + c] = l;
    }
    __syncthreads();

    if (is_img) {
        uint32_t* dst = g_imgA + (size_t)bid * TILE_U32;
        #pragma unroll 4
        for (int w = 0; w < 16; w++) {
            int idx = w * 512 + tid;
            int reg = idx & 3, lane = (idx >> 2) & 31, ks = (idx >> 7) & 3;
            int m16 = (idx >> 9) & 7, pass = idx >> 12;
            int row = 16 * m16 + (lane >> 2) + 8 * (reg & 1);
            int k = 32 * ks + 4 * (lane & 3) + 16 * (reg >> 1);
            const char* s = pass ? sl : sh;
            dst[idx] = *(const uint32_t*)(s + row * 132 + k);
        }
    } else {
        uint32_t* dst = g_refsQ + (size_t)(bid - MTILES) * TILE_U32;
        #pragma unroll 4
        for (int w = 0; w < 16; w++) {
            int idx = w * 512 + tid;
            int reg = idx & 3, lane = (idx >> 2) & 31, ks = (idx >> 7) & 3;
            int nfp = (idx >> 9) & 7, pass = idx >> 12;
            int col = 16 * nfp + (lane >> 2) + 8 * (reg >> 1);
            int k = 32 * ks + 4 * (lane & 3) + 16 * (reg & 1);
            const char* s = pass ? sl : sh;
            dst[idx] = *(const uint32_t*)(s + col * 132 + k);
        }
    }
}

// ============================================================================
// K2: main GEMM+max. CTA=(bm,bn) x 576 (work-stealing balance), 2 CTAs/SM.
// 8 warps 4(M)x2(N), warp 32x64. A hi+lo in regs; B 3-stage cp.async ring.
// Mid-iteration barrier + next-tile np0 preload.
// ============================================================================
__device__ __forceinline__ void fill_b_async(uint32_t dst,
                                             const uint32_t* __restrict__ src,
                                             int tid) {
    const char* s = (const char*)src;
    #pragma unroll
    for (int i = 0; i < 8; i++)
        CP_ASYNC16(dst + i * 4096 + tid * 16, s + i * 4096 + tid * 16);
}

__global__ __launch_bounds__(256, 2) void k_gemm_max(float* __restrict__ out) {
    extern __shared__ char sm[];
    __shared__ int s_last;
    const int tid = threadIdx.x, wid = tid >> 5, lane = tid & 31;
    const int wm = wid >> 1, wn = wid & 1;
    const uint32_t Bring = smem_u32(sm);         // 3 x 32KB

    const int bm = blockIdx.x % MTILES;
    const int bn = blockIdx.x / MTILES;
    const int p0 = bm * MT;
    const uint32_t* imgT = g_imgA + (size_t)bm * TILE_U32;
    const uint32_t* refT = g_refsQ + (size_t)(bn * NTILES) * TILE_U32;

    // prologue: fill tiles 0 and 1 as two commit groups
    fill_b_async(Bring, refT, tid);
    CP_COMMIT();
    fill_b_async(Bring + BSTAGE_BYTES, refT + TILE_U32, tid);
    CP_COMMIT();

    // A hi+lo fragments -> registers (live whole kernel)
    uint32_t ahi[2][4][4], alo[2][4][4];
    #pragma unroll
    for (int mf = 0; mf < 2; mf++)
        #pragma unroll
        for (int ks = 0; ks < 4; ks++) {
            const size_t fi = (size_t)(((wm * 2 + mf) * 4 + ks) * 32 + lane) * 4;
            const uint4 wh = *(const uint4*)(imgT + fi);
            const uint4 wl = *(const uint4*)(imgT + 4096 + fi);
            ahi[mf][ks][0] = wh.x; ahi[mf][ks][1] = wh.y;
            ahi[mf][ks][2] = wh.z; ahi[mf][ks][3] = wh.w;
            alo[mf][ks][0] = wl.x; alo[mf][ks][1] = wl.y;
            alo[mf][ks][2] = wl.z; alo[mf][ks][3] = wl.w;
        }

    const uint32_t bOffW = (uint32_t)((wn * 4) * 4 * 32 + lane) * 16;

    int rmax0[2], rmax1[2];
    #pragma unroll
    for (int mf = 0; mf < 2; mf++) { rmax0[mf] = (int)0x80000000; rmax1[mf] = (int)0x80000000; }

    // prologue sync: tile 0 visible (fill(0) retired), then preload its np0
    CP_WAIT(1);
    __syncthreads();
    uint32_t pbh[4], pbl[4];
    {
        const uint32_t Bh = Bring + bOffW;
        LDS128(pbh[0], pbh[1], pbh[2], pbh[3], Bh);
        LDS128(pbl[0], pbl[1], pbl[2], pbl[3], Bh + 16384);
    }

    #pragma unroll 1
    for (int t = 0; t < NTILES; t++) {
        // fill stage (t+2)%3; its last readers (tile t-1) finished all LDS
        // before the mid-iteration barrier of t-1, which precedes this point.
        // One commit group per iteration (empty at tail is legal).
        if (t + 2 < NTILES)
            fill_b_async(Bring + (uint32_t)((t + 2) % 3) * BSTAGE_BYTES,
                         refT + (size_t)(t + 2) * TILE_U32, tid);
        CP_COMMIT();

        const uint32_t Bhi = Bring + (uint32_t)(t % 3) * BSTAGE_BYTES + bOffW;
        const uint32_t Blo = Bhi + 16384;

        #pragma unroll
        for (int np = 0; np < 4; np++) {
            int hh[2][2][4], xx[2][2][4];
            #pragma unroll
            for (int ks = 0; ks < 4; ks++) {
                uint32_t bh[4], bl[4];
                if (np == 0 && ks == 0) {
                    bh[0] = pbh[0]; bh[1] = pbh[1]; bh[2] = pbh[2]; bh[3] = pbh[3];
                    bl[0] = pbl[0]; bl[1] = pbl[1]; bl[2] = pbl[2]; bl[3] = pbl[3];
                } else {
                    const uint32_t fo = (uint32_t)((np * 4 + ks) * 32) * 16;
                    LDS128(bh[0], bh[1], bh[2], bh[3], Bhi + fo);
                    LDS128(bl[0], bl[1], bl[2], bl[3], Blo + fo);
                }
                #pragma unroll
                for (int half = 0; half < 2; half++) {
                    const uint32_t* bhp = bh + 2 * half;
                    const uint32_t* blp = bl + 2 * half;
                    #pragma unroll
                    for (int mf = 0; mf < 2; mf++) {
                        if (ks == 0) {
                            mma_s8_zc(hh[mf][half], ahi[mf][0], bhp);
                            mma_s8_zc(xx[mf][half], ahi[mf][0], blp);
                            mma_s8(xx[mf][half], alo[mf][0], bhp);
                        } else {
                            mma_s8(hh[mf][half], ahi[mf][ks], bhp);
                            mma_s8(xx[mf][half], ahi[mf][ks], blp);
                            mma_s8(xx[mf][half], alo[mf][ks], bhp);
                        }
                    }
                }
            }

            if (np == 3) {
                // mid-iteration sync: WAIT(1) retires fill(t+1); the barrier
                // publishes it and retires all reads of tile t. Then preload
                // tile t+1's np0 fragments (latency hides under the fold).
                CP_WAIT(1);
                __syncthreads();
                if (t + 1 < NTILES) {
                    const uint32_t Bn = Bring +
                        (uint32_t)((t + 1) % 3) * BSTAGE_BYTES + bOffW;
                    LDS128(pbh[0], pbh[1], pbh[2], pbh[3], Bn);
                    LDS128(pbl[0], pbl[1], pbl[2], pbl[3], Bn + 16384);
                }
            }

            // fold this np-group
            #pragma unroll
            for (int mf = 0; mf < 2; mf++)
                #pragma unroll
                for (int h = 0; h < 2; h++) {
                    int s0 = hh[mf][h][0] * 128 + xx[mf][h][0];
                    int s1 = hh[mf][h][1] * 128 + xx[mf][h][1];
                    int s2 = hh[mf][h][2] * 128 + xx[mf][h][2];
                    int s3 = hh[mf][h][3] * 128 + xx[mf][h][3];
                    rmax0[mf] = max(rmax0[mf], max(s0, s1));
                    rmax1[mf] = max(rmax1[mf], max(s2, s3));
                }
        }
    }

    // per-CTA epilogue: reduce 4 lanes sharing a row, one atomic per row
    #pragma unroll
    for (int mf = 0; mf < 2; mf++) {
        int m0 = rmax0[mf], m1 = rmax1[mf];
        m0 = max(m0, __shfl_xor_sync(0xffffffffu, m0, 1));
        m0 = max(m0, __shfl_xor_sync(0xffffffffu, m0, 2));
        m1 = max(m1, __shfl_xor_sync(0xffffffffu, m1, 1));
        m1 = max(m1, __shfl_xor_sync(0xffffffffu, m1, 2));
        if ((lane & 3) == 0) {
            int row = p0 + wm * 32 + mf * 16 + (lane >> 2);
            atomicMax(&g_pmax[row], m0);
            atomicMax(&g_pmax[row + 8], m1);
        }
    }

    // last-block final decode
    __threadfence();
    if (tid == 0) s_last = (atomicAdd(&g_done, 1) == NBLK - 1);
    __syncthreads();
    if (s_last) {
        #pragma unroll
        for (int i = 0; i < HW / 256; i++) {
            int p = i * 256 + tid;
            int s = atomicMax(&g_pmax[p], (int)0x80000000);
            out[p] = (float)s * (1.0f / 2097152.0f);
        }
    }
}

// ============================================================================
extern "C" void kernel_launch(void* const* d_in, const int* in_sizes, int n_in,
                              void* d_out, int out_size) {
    const float* refs = (const float*)d_in[0];
    const float* img  = (const float*)d_in[1];
    float* out = (float*)d_out;

    cudaFuncSetAttribute(k_gemm_max, cudaFuncAttributeMaxDynamicSharedMemorySize,
                         DSMEM_GEMM);

    k_prep<<<MTILES + NREF * NTILES, 512, PREP_SMEM>>>(refs, img);
    k_gemm_max<<<NBLK, 256, DSMEM_GEMM>>>(out);
}